// round 6
// baseline (speedup 1.0000x reference)
#include <cuda_runtime.h>
#include <cuda_fp16.h>
#include <cstdint>

// PolyConv: CSR build + degree-sorted atomic-free fused iterations.
// State fp32 in-place; gather fp32 (iter1) then fp16 ping-pong (iters 2-4).
// Inputs: feat [N*32 f32], src [E i32], dst [E i32], mask [E f32]
// Output: h [N*32 f32]

#define N_NODES 100000
#define N_EDGES 1600000
#define DFEAT   32
#define DV4     (DFEAT / 4)        // 8 float4 per node row
#define NV4     (N_NODES * DV4)
#define NH4     (N_NODES * 4)      // 4 uint4 (8 halves) per node row

#define SCAN_B  1024
#define N_SBLK  ((N_NODES + SCAN_B - 1) / SCAN_B)   // 98
#define BINS    256

// ---- scratch (static __device__, no allocation) ----
__device__ int    g_cnt[N_NODES];
__device__ float  g_degf[N_NODES];
__device__ int    g_row[N_NODES + 1];
__device__ int    g_cursor[N_NODES];
__device__ int    g_bsum[N_SBLK];
__device__ float2 g_fac[N_NODES];        // {dinv^2, sqrt(max(deg,1))}
__device__ int2   g_edges[N_EDGES];      // CSR: {src, mask_bits} grouped by dst
__device__ int    g_dbin[BINS];          // degree-bin counts
__device__ int    g_dcur[BINS];          // degree-bin cursors (offsets)
__device__ int    g_perm[N_NODES];       // degree-sorted node order (descending)
__device__ float4 g_src32[NV4];          // fp32 gather source for iter1 (= T0 scaled)
__device__ float4 g_scaled[NV4];         // fp32 state, in-place (iters >= 1 write)
__device__ uint4  g_halfA[NH4];          // fp16 gather copy (ping)
__device__ uint4  g_halfB[NH4];          // fp16 gather copy (pong)

static __device__ __forceinline__ unsigned h2u(__half2 h) {
    return *reinterpret_cast<unsigned*>(&h);
}

// ---------------------------------------------------------------------------
__global__ void k_zero() {
    int i = blockIdx.x * blockDim.x + threadIdx.x;
    if (i < N_NODES) { g_cnt[i] = 0; g_degf[i] = 0.0f; }
    if (i < BINS) g_dbin[i] = 0;
}

__global__ void k_hist(const int* __restrict__ dst, const float* __restrict__ mask, int E) {
    int e = blockIdx.x * blockDim.x + threadIdx.x;
    if (e < E) {
        int d = dst[e];
        atomicAdd(&g_cnt[d], 1);
        atomicAdd(&g_degf[d], mask[e]);
    }
}

// scan stage 1: per-block exclusive scan of g_cnt -> g_row, block totals -> g_bsum
__global__ void k_scan1() {
    __shared__ int sh[SCAN_B];
    int t = threadIdx.x;
    int gid = blockIdx.x * SCAN_B + t;
    int v = (gid < N_NODES) ? g_cnt[gid] : 0;
    sh[t] = v;
    __syncthreads();
    for (int off = 1; off < SCAN_B; off <<= 1) {
        int x = (t >= off) ? sh[t - off] : 0;
        __syncthreads();
        sh[t] += x;
        __syncthreads();
    }
    int incl = sh[t];
    if (gid < N_NODES) g_row[gid] = incl - v;
    if (t == SCAN_B - 1) g_bsum[blockIdx.x] = incl;
}

// stage 2+3: warp-reduce prior block totals, apply offset, init cursor,
// compute node factors, and histogram degrees into bins (descending order).
__global__ void k_scan23(int E) {
    __shared__ int s_prefix;
    int t = threadIdx.x;
    if (t < 32) {
        int sum = 0;
        for (int b = t; b < N_SBLK; b += 32)
            if (b < (int)blockIdx.x) sum += g_bsum[b];
        #pragma unroll
        for (int o = 16; o; o >>= 1) sum += __shfl_xor_sync(0xFFFFFFFFu, sum, o);
        if (t == 0) s_prefix = sum;
    }
    __syncthreads();
    int prefix = s_prefix;

    int gid = blockIdx.x * SCAN_B + t;
    if (gid < N_NODES) {
        int r = g_row[gid] + prefix;
        g_row[gid] = r;
        g_cursor[gid] = r;
        float deg = fmaxf(g_degf[gid], 1.0f);
        float dinv = rsqrtf(deg);
        g_fac[gid] = make_float2(dinv * dinv, deg * dinv);  // {dinv^2, sqrt(deg)}
        int cnt = g_cnt[gid];
        int bin = (BINS - 1) - min(cnt, BINS - 1);          // descending degree
        atomicAdd(&g_dbin[bin], 1);
    }
    if (gid == 0) g_row[N_NODES] = E;
}

// exclusive prefix over 256 degree bins -> cursors
__global__ void k_dprefix() {
    __shared__ int sh[BINS];
    int t = threadIdx.x;
    int v = g_dbin[t];
    sh[t] = v;
    __syncthreads();
    for (int o = 1; o < BINS; o <<= 1) {
        int x = (t >= o) ? sh[t - o] : 0;
        __syncthreads();
        sh[t] += x;
        __syncthreads();
    }
    g_dcur[t] = sh[t] - v;
}

__global__ void k_scatter(const int* __restrict__ src, const int* __restrict__ dst,
                          const float* __restrict__ mask, int E) {
    int e = blockIdx.x * blockDim.x + threadIdx.x;
    if (e >= E) return;
    int d = dst[e];
    int pos = atomicAdd(&g_cursor[d], 1);
    g_edges[pos] = make_int2(src[e], __float_as_int(mask[e]));
}

// counting-sort scatter of node ids into degree-descending order
__global__ void k_dscatter() {
    int i = blockIdx.x * blockDim.x + threadIdx.x;
    if (i >= N_NODES) return;
    int bin = (BINS - 1) - min(g_cnt[i], BINS - 1);
    int pos = atomicAdd(&g_dcur[bin], 1);
    g_perm[pos] = i;
}

// init: g_src32 = feat * dinv (fp32 T0-scaled, gather source for iter1)
__global__ void k_init(const float4* __restrict__ feat4) {
    int i = blockIdx.x * blockDim.x + threadIdx.x;
    if (i >= NV4) return;
    int n = i >> 3;
    float dinv = rsqrtf(fmaxf(g_degf[n], 1.0f));
    float4 f = feat4[i];
    float4 s;
    s.x = f.x * dinv; s.y = f.y * dinv; s.z = f.z * dinv; s.w = f.w * dinv;
    g_src32[i] = s;
}

// iteration 1: fp32 gather from g_src32; h pure-write (theta0*T0 + theta1*T1);
// writes fp32 state g_scaled and fp16 copy g_halfB. 4 lanes/node.
__global__ void __launch_bounds__(256)
k_iter1(float4* __restrict__ h4, float theta0, float theta1) {
    int t = threadIdx.x;
    int g = blockIdx.x * 64 + (t >> 2);
    if (g >= N_NODES) return;
    int n = g_perm[g];
    int c = t & 3;

    int base = g_row[n];
    int end  = g_row[n + 1];

    float a0 = 0.f, a1 = 0.f, a2 = 0.f, a3 = 0.f;
    float a4 = 0.f, a5 = 0.f, a6 = 0.f, a7 = 0.f;

    #pragma unroll 2
    for (int j = base; j < end; ++j) {
        int2 ed = g_edges[j];
        float m = __int_as_float(ed.y);
        const float4* p = &g_src32[ed.x * DV4 + c * 2];
        float4 v0 = p[0], v1 = p[1];
        a0 += v0.x * m; a1 += v0.y * m; a2 += v0.z * m; a3 += v0.w * m;
        a4 += v1.x * m; a5 += v1.y * m; a6 += v1.z * m; a7 += v1.w * m;
    }

    float2 fac = g_fac[n];
    float dinv2 = fac.x, rsq = fac.y;

    int i0 = n * DV4 + c * 2;
    float4 o0 = g_src32[i0], o1 = g_src32[i0 + 1];   // s_old (T0 scaled)
    float4 s0, s1;
    s0.x = o0.x - a0 * dinv2; s0.y = o0.y - a1 * dinv2;
    s0.z = o0.z - a2 * dinv2; s0.w = o0.w - a3 * dinv2;
    s1.x = o1.x - a4 * dinv2; s1.y = o1.y - a5 * dinv2;
    s1.z = o1.z - a6 * dinv2; s1.w = o1.w - a7 * dinv2;
    g_scaled[i0] = s0;
    g_scaled[i0 + 1] = s1;

    float tpr = theta0 * rsq, tr = theta1 * rsq;
    float4 h0, h1;
    h0.x = tpr * o0.x + tr * s0.x; h0.y = tpr * o0.y + tr * s0.y;
    h0.z = tpr * o0.z + tr * s0.z; h0.w = tpr * o0.w + tr * s0.w;
    h1.x = tpr * o1.x + tr * s1.x; h1.y = tpr * o1.y + tr * s1.y;
    h1.z = tpr * o1.z + tr * s1.z; h1.w = tpr * o1.w + tr * s1.w;
    h4[i0] = h0;
    h4[i0 + 1] = h1;

    uint4 hp;
    hp.x = h2u(__floats2half2_rn(s0.x, s0.y));
    hp.y = h2u(__floats2half2_rn(s0.z, s0.w));
    hp.z = h2u(__floats2half2_rn(s1.x, s1.y));
    hp.w = h2u(__floats2half2_rn(s1.z, s1.w));
    g_halfB[n * 4 + c] = hp;
}

// iterations 2-4: fp16 gather, in-place fp32 state, h accumulate.
// sel: 1 -> in=halfA out=halfB, 0 -> in=halfB out=halfA.
// write_next: write the fp16 copy for the next iteration.
__global__ void __launch_bounds__(256)
k_iter(float4* __restrict__ h4, float theta, int write_next, int sel) {
    const uint4* __restrict__ gin  = sel ? g_halfA : g_halfB;
    uint4* __restrict__       gout = sel ? g_halfB : g_halfA;

    int t = threadIdx.x;
    int g = blockIdx.x * 64 + (t >> 2);
    if (g >= N_NODES) return;
    int n = g_perm[g];
    int c = t & 3;

    int base = g_row[n];
    int end  = g_row[n + 1];

    float a0 = 0.f, a1 = 0.f, a2 = 0.f, a3 = 0.f;
    float a4 = 0.f, a5 = 0.f, a6 = 0.f, a7 = 0.f;

    #pragma unroll 4
    for (int j = base; j < end; ++j) {
        int2 ed = g_edges[j];
        float m = __int_as_float(ed.y);
        uint4 v = gin[ed.x * 4 + c];
        float2 f;
        f = __half22float2(*reinterpret_cast<__half2*>(&v.x)); a0 += f.x * m; a1 += f.y * m;
        f = __half22float2(*reinterpret_cast<__half2*>(&v.y)); a2 += f.x * m; a3 += f.y * m;
        f = __half22float2(*reinterpret_cast<__half2*>(&v.z)); a4 += f.x * m; a5 += f.y * m;
        f = __half22float2(*reinterpret_cast<__half2*>(&v.w)); a6 += f.x * m; a7 += f.y * m;
    }

    float2 fac = g_fac[n];
    float dinv2 = fac.x, rsq = fac.y;

    int i0 = n * DV4 + c * 2;
    float4 s0 = g_scaled[i0], s1 = g_scaled[i0 + 1];
    s0.x -= a0 * dinv2; s0.y -= a1 * dinv2; s0.z -= a2 * dinv2; s0.w -= a3 * dinv2;
    s1.x -= a4 * dinv2; s1.y -= a5 * dinv2; s1.z -= a6 * dinv2; s1.w -= a7 * dinv2;
    g_scaled[i0] = s0;
    g_scaled[i0 + 1] = s1;

    float tr = theta * rsq;
    float4 h0 = h4[i0], h1 = h4[i0 + 1];
    h0.x += tr * s0.x; h0.y += tr * s0.y; h0.z += tr * s0.z; h0.w += tr * s0.w;
    h1.x += tr * s1.x; h1.y += tr * s1.y; h1.z += tr * s1.z; h1.w += tr * s1.w;
    h4[i0] = h0;
    h4[i0 + 1] = h1;

    if (write_next) {
        uint4 hp;
        hp.x = h2u(__floats2half2_rn(s0.x, s0.y));
        hp.y = h2u(__floats2half2_rn(s0.z, s0.w));
        hp.z = h2u(__floats2half2_rn(s1.x, s1.y));
        hp.w = h2u(__floats2half2_rn(s1.z, s1.w));
        gout[n * 4 + c] = hp;
    }
}

extern "C" void kernel_launch(void* const* d_in, const int* in_sizes, int n_in,
                              void* d_out, int out_size) {
    const float* feat = (const float*)d_in[0];
    const int*   src  = (const int*)d_in[1];
    const int*   dst  = (const int*)d_in[2];
    const float* mask = (const float*)d_in[3];
    float* out = (float*)d_out;

    const int E = in_sizes[1];
    const int TB = 256;

    // --- CSR build + degree sort ---
    k_zero<<<(N_NODES + TB - 1) / TB, TB>>>();
    k_hist<<<(E + TB - 1) / TB, TB>>>(dst, mask, E);
    k_scan1<<<N_SBLK, SCAN_B>>>();
    k_scan23<<<N_SBLK, SCAN_B>>>(E);
    k_dprefix<<<1, BINS>>>();
    k_scatter<<<(E + TB - 1) / TB, TB>>>(src, dst, mask, E);
    k_dscatter<<<(N_NODES + TB - 1) / TB, TB>>>();

    // --- init ---
    k_init<<<(NV4 + TB - 1) / TB, TB>>>((const float4*)feat);

    // --- 4 fused iterations ---
    // theta = {0.2, -0.4, 0.3, -0.15, 0.05}
    int iter_blocks = (N_NODES + 63) / 64;

    k_iter1<<<iter_blocks, TB>>>((float4*)out, 0.2f, -0.4f);
    k_iter<<<iter_blocks, TB>>>((float4*)out, 0.3f,   1, 0);  // reads B, writes A
    k_iter<<<iter_blocks, TB>>>((float4*)out, -0.15f, 1, 1);  // reads A, writes B
    k_iter<<<iter_blocks, TB>>>((float4*)out, 0.05f,  0, 0);  // reads B
}

// round 7
// speedup vs baseline: 1.2891x; 1.2891x over previous
#include <cuda_runtime.h>
#include <cuda_fp16.h>
#include <cstdint>

// PolyConv: CSR build + atomic-free fused iterations (natural node order).
// State fp32 in-place; gather fp32 (iter1) then fp16 ping-pong (iters 2-4).
// Inputs: feat [N*32 f32], src [E i32], dst [E i32], mask [E f32]
// Output: h [N*32 f32]

#define N_NODES 100000
#define N_EDGES 1600000
#define DFEAT   32
#define DV4     (DFEAT / 4)        // 8 float4 per node row
#define NV4     (N_NODES * DV4)
#define NH4     (N_NODES * 4)      // 4 uint4 (8 halves) per node row

#define SCAN_B  1024
#define N_SBLK  ((N_NODES + SCAN_B - 1) / SCAN_B)   // 98

// ---- scratch (static __device__, no allocation) ----
__device__ int    g_cnt[N_NODES];
__device__ int    g_row[N_NODES + 1];
__device__ int    g_cursor[N_NODES];
__device__ int    g_bsum[N_SBLK];
__device__ float2 g_fac[N_NODES];        // {dinv^2, sqrt(max(deg,1))}
__device__ int2   g_edges[N_EDGES];      // CSR: {src, mask_bits} grouped by dst
__device__ float4 g_src32[NV4];          // fp32 gather source for iter1 (T0 scaled)
__device__ float4 g_scaled[NV4];         // fp32 state, in-place
__device__ uint4  g_halfA[NH4];          // fp16 gather copy (ping)
__device__ uint4  g_halfB[NH4];          // fp16 gather copy (pong)

static __device__ __forceinline__ unsigned h2u(__half2 h) {
    return *reinterpret_cast<unsigned*>(&h);
}

// ---------------------------------------------------------------------------
__global__ void k_zero() {
    int i = blockIdx.x * blockDim.x + threadIdx.x;
    if (i < N_NODES) g_cnt[i] = 0;
}

// histogram: edge count per dst (single int atomic per edge)
__global__ void k_hist(const int* __restrict__ dst, int E) {
    int e = blockIdx.x * blockDim.x + threadIdx.x;
    if (e < E) atomicAdd(&g_cnt[dst[e]], 1);
}

// scan stage 1: shuffle-based per-block exclusive scan of g_cnt -> g_row,
// block totals -> g_bsum.
__global__ void k_scan1() {
    __shared__ int warp_sums[32];
    int t = threadIdx.x;
    int lane = t & 31, warp = t >> 5;
    int gid = blockIdx.x * SCAN_B + t;
    int v = (gid < N_NODES) ? g_cnt[gid] : 0;

    // inclusive scan within warp
    int x = v;
    #pragma unroll
    for (int o = 1; o < 32; o <<= 1) {
        int y = __shfl_up_sync(0xFFFFFFFFu, x, o);
        if (lane >= o) x += y;
    }
    if (lane == 31) warp_sums[warp] = x;
    __syncthreads();
    if (warp == 0) {
        int s = warp_sums[lane];
        #pragma unroll
        for (int o = 1; o < 32; o <<= 1) {
            int y = __shfl_up_sync(0xFFFFFFFFu, s, o);
            if (lane >= o) s += y;
        }
        warp_sums[lane] = s;
    }
    __syncthreads();
    int warp_off = (warp > 0) ? warp_sums[warp - 1] : 0;
    int incl = x + warp_off;
    if (gid < N_NODES) g_row[gid] = incl - v;          // exclusive
    if (t == SCAN_B - 1) g_bsum[blockIdx.x] = incl;    // block total
}

// stage 2+3: warp-reduce prior block totals, apply offset, init cursor.
__global__ void k_scan23(int E) {
    __shared__ int s_prefix;
    int t = threadIdx.x;
    if (t < 32) {
        int sum = 0;
        for (int b = t; b < (int)blockIdx.x; b += 32) sum += g_bsum[b];
        #pragma unroll
        for (int o = 16; o; o >>= 1) sum += __shfl_xor_sync(0xFFFFFFFFu, sum, o);
        if (t == 0) s_prefix = sum;
    }
    __syncthreads();
    int prefix = s_prefix;

    int gid = blockIdx.x * SCAN_B + t;
    if (gid < N_NODES) {
        int r = g_row[gid] + prefix;
        g_row[gid] = r;
        g_cursor[gid] = r;
    }
    if (gid == 0) g_row[N_NODES] = E;
}

__global__ void k_scatter(const int* __restrict__ src, const int* __restrict__ dst,
                          const float* __restrict__ mask, int E) {
    int e = blockIdx.x * blockDim.x + threadIdx.x;
    if (e >= E) return;
    int d = dst[e];
    int pos = atomicAdd(&g_cursor[d], 1);
    g_edges[pos] = make_int2(src[e], __float_as_int(mask[e]));
}

// fused fac + init: 4 lanes per node. Sum masks over CSR row (shuffle-reduce),
// compute factors, write src32 = feat*dinv (coalesced 2 float4 per lane).
__global__ void __launch_bounds__(256)
k_facinit(const float4* __restrict__ feat4) {
    int t = threadIdx.x;
    int n = blockIdx.x * 64 + (t >> 2);
    if (n >= N_NODES) return;
    int c = t & 3;

    int base = g_row[n];
    int end  = g_row[n + 1];
    float deg = 0.0f;
    for (int j = base + c; j < end; j += 4)
        deg += __int_as_float(g_edges[j].y);
    deg += __shfl_xor_sync(0xFFFFFFFFu, deg, 1);
    deg += __shfl_xor_sync(0xFFFFFFFFu, deg, 2);

    deg = fmaxf(deg, 1.0f);
    float dinv = rsqrtf(deg);
    if (c == 0) g_fac[n] = make_float2(dinv * dinv, deg * dinv); // {dinv^2, sqrt(deg)}

    int i0 = n * DV4 + c * 2;
    float4 f0 = feat4[i0], f1 = feat4[i0 + 1];
    float4 s0, s1;
    s0.x = f0.x * dinv; s0.y = f0.y * dinv; s0.z = f0.z * dinv; s0.w = f0.w * dinv;
    s1.x = f1.x * dinv; s1.y = f1.y * dinv; s1.z = f1.z * dinv; s1.w = f1.w * dinv;
    g_src32[i0] = s0;
    g_src32[i0 + 1] = s1;
}

// iteration 1: fp32 gather from g_src32; h pure-write (theta0*T0 + theta1*T1);
// writes fp32 state g_scaled and fp16 copy g_halfB. 4 lanes/node.
__global__ void __launch_bounds__(256)
k_iter1(float4* __restrict__ h4, float theta0, float theta1) {
    int t = threadIdx.x;
    int n = blockIdx.x * 64 + (t >> 2);
    if (n >= N_NODES) return;
    int c = t & 3;

    int base = g_row[n];
    int end  = g_row[n + 1];

    float a0 = 0.f, a1 = 0.f, a2 = 0.f, a3 = 0.f;
    float a4 = 0.f, a5 = 0.f, a6 = 0.f, a7 = 0.f;

    #pragma unroll 2
    for (int j = base; j < end; ++j) {
        int2 ed = g_edges[j];
        float m = __int_as_float(ed.y);
        const float4* p = &g_src32[ed.x * DV4 + c * 2];
        float4 v0 = p[0], v1 = p[1];
        a0 += v0.x * m; a1 += v0.y * m; a2 += v0.z * m; a3 += v0.w * m;
        a4 += v1.x * m; a5 += v1.y * m; a6 += v1.z * m; a7 += v1.w * m;
    }

    float2 fac = g_fac[n];
    float dinv2 = fac.x, rsq = fac.y;

    int i0 = n * DV4 + c * 2;
    float4 o0 = g_src32[i0], o1 = g_src32[i0 + 1];
    float4 s0, s1;
    s0.x = o0.x - a0 * dinv2; s0.y = o0.y - a1 * dinv2;
    s0.z = o0.z - a2 * dinv2; s0.w = o0.w - a3 * dinv2;
    s1.x = o1.x - a4 * dinv2; s1.y = o1.y - a5 * dinv2;
    s1.z = o1.z - a6 * dinv2; s1.w = o1.w - a7 * dinv2;
    g_scaled[i0] = s0;
    g_scaled[i0 + 1] = s1;

    float tpr = theta0 * rsq, tr = theta1 * rsq;
    float4 h0, h1;
    h0.x = tpr * o0.x + tr * s0.x; h0.y = tpr * o0.y + tr * s0.y;
    h0.z = tpr * o0.z + tr * s0.z; h0.w = tpr * o0.w + tr * s0.w;
    h1.x = tpr * o1.x + tr * s1.x; h1.y = tpr * o1.y + tr * s1.y;
    h1.z = tpr * o1.z + tr * s1.z; h1.w = tpr * o1.w + tr * s1.w;
    h4[i0] = h0;
    h4[i0 + 1] = h1;

    uint4 hp;
    hp.x = h2u(__floats2half2_rn(s0.x, s0.y));
    hp.y = h2u(__floats2half2_rn(s0.z, s0.w));
    hp.z = h2u(__floats2half2_rn(s1.x, s1.y));
    hp.w = h2u(__floats2half2_rn(s1.z, s1.w));
    g_halfB[n * 4 + c] = hp;
}

// iterations 2-4: fp16 gather, in-place fp32 state, h accumulate.
// sel: 1 -> in=halfA out=halfB, 0 -> in=halfB out=halfA.
__global__ void __launch_bounds__(256)
k_iter(float4* __restrict__ h4, float theta, int write_next, int sel) {
    const uint4* __restrict__ gin  = sel ? g_halfA : g_halfB;
    uint4* __restrict__       gout = sel ? g_halfB : g_halfA;

    int t = threadIdx.x;
    int n = blockIdx.x * 64 + (t >> 2);
    if (n >= N_NODES) return;
    int c = t & 3;

    int base = g_row[n];
    int end  = g_row[n + 1];

    float a0 = 0.f, a1 = 0.f, a2 = 0.f, a3 = 0.f;
    float a4 = 0.f, a5 = 0.f, a6 = 0.f, a7 = 0.f;

    #pragma unroll 8
    for (int j = base; j < end; ++j) {
        int2 ed = g_edges[j];
        float m = __int_as_float(ed.y);
        uint4 v = gin[ed.x * 4 + c];
        float2 f;
        f = __half22float2(*reinterpret_cast<__half2*>(&v.x)); a0 += f.x * m; a1 += f.y * m;
        f = __half22float2(*reinterpret_cast<__half2*>(&v.y)); a2 += f.x * m; a3 += f.y * m;
        f = __half22float2(*reinterpret_cast<__half2*>(&v.z)); a4 += f.x * m; a5 += f.y * m;
        f = __half22float2(*reinterpret_cast<__half2*>(&v.w)); a6 += f.x * m; a7 += f.y * m;
    }

    float2 fac = g_fac[n];
    float dinv2 = fac.x, rsq = fac.y;

    int i0 = n * DV4 + c * 2;
    float4 s0 = g_scaled[i0], s1 = g_scaled[i0 + 1];
    s0.x -= a0 * dinv2; s0.y -= a1 * dinv2; s0.z -= a2 * dinv2; s0.w -= a3 * dinv2;
    s1.x -= a4 * dinv2; s1.y -= a5 * dinv2; s1.z -= a6 * dinv2; s1.w -= a7 * dinv2;
    g_scaled[i0] = s0;
    g_scaled[i0 + 1] = s1;

    float tr = theta * rsq;
    float4 h0 = h4[i0], h1 = h4[i0 + 1];
    h0.x += tr * s0.x; h0.y += tr * s0.y; h0.z += tr * s0.z; h0.w += tr * s0.w;
    h1.x += tr * s1.x; h1.y += tr * s1.y; h1.z += tr * s1.z; h1.w += tr * s1.w;
    h4[i0] = h0;
    h4[i0 + 1] = h1;

    if (write_next) {
        uint4 hp;
        hp.x = h2u(__floats2half2_rn(s0.x, s0.y));
        hp.y = h2u(__floats2half2_rn(s0.z, s0.w));
        hp.z = h2u(__floats2half2_rn(s1.x, s1.y));
        hp.w = h2u(__floats2half2_rn(s1.z, s1.w));
        gout[n * 4 + c] = hp;
    }
}

extern "C" void kernel_launch(void* const* d_in, const int* in_sizes, int n_in,
                              void* d_out, int out_size) {
    const float* feat = (const float*)d_in[0];
    const int*   src  = (const int*)d_in[1];
    const int*   dst  = (const int*)d_in[2];
    const float* mask = (const float*)d_in[3];
    float* out = (float*)d_out;

    const int E = in_sizes[1];
    const int TB = 256;

    // --- CSR build ---
    k_zero<<<(N_NODES + TB - 1) / TB, TB>>>();
    k_hist<<<(E + TB - 1) / TB, TB>>>(dst, E);
    k_scan1<<<N_SBLK, SCAN_B>>>();
    k_scan23<<<N_SBLK, SCAN_B>>>(E);
    k_scatter<<<(E + TB - 1) / TB, TB>>>(src, dst, mask, E);

    // --- factors + init (fused) ---
    int node4_blocks = (N_NODES + 63) / 64;
    k_facinit<<<node4_blocks, TB>>>((const float4*)feat);

    // --- 4 fused iterations ---  theta = {0.2, -0.4, 0.3, -0.15, 0.05}
    k_iter1<<<node4_blocks, TB>>>((float4*)out, 0.2f, -0.4f);
    k_iter<<<node4_blocks, TB>>>((float4*)out, 0.3f,   1, 0);  // reads B, writes A
    k_iter<<<node4_blocks, TB>>>((float4*)out, -0.15f, 1, 1);  // reads A, writes B
    k_iter<<<node4_blocks, TB>>>((float4*)out, 0.05f,  0, 0);  // reads B
}